// round 4
// baseline (speedup 1.0000x reference)
#include <cuda_runtime.h>
#include <cuda_bf16.h>
#include <cstdint>
#include <math.h>

#define TAU 0.5f
#define B 16
#define H 96
#define W 96
#define NPIX (H*W)
#define NB (2*B)       // 32 blocks: (image, direction)
#define NT 768         // threads per block

// static device scratch (no allocation)
__device__ int g_maxAB[B];
__device__ int g_maxBA[B];
__device__ int g_anyA[B];
__device__ int g_anyB[B];
__device__ int g_done = 0;

// ---------------------------------------------------------------------------
// One kernel does everything.
// block (img, dir): dir 0 computes max over pred-pixels of min-d2 to label set;
// dir 1 the reverse. Separable EDT: column row-distance scan (u8) + exact
// early-exit 1D min-plus. Last block finalizes mean.
// ---------------------------------------------------------------------------
__global__ void __launch_bounds__(NT, 1)
hd_all(const float* __restrict__ pred,
       const float* __restrict__ tgt,
       float* __restrict__ out)
{
    const int bx  = blockIdx.x;
    const int img = bx >> 1;
    const int dir = bx & 1;
    const int tid = threadIdx.x;
    const int lane = tid & 31;
    const int wid  = tid >> 5;

    const float* srcQ = dir ? (tgt  + img * NPIX) : (pred + img * NPIX);
    const float* srcT = dir ? (pred + img * NPIX) : (tgt  + img * NPIX);

    __shared__ uint8_t mq[NPIX];    // query mask
    __shared__ uint8_t mt[NPIX];    // target mask
    __shared__ uint8_t dF[NPIX];    // forward (top->down) row distance to target
    __shared__ uint8_t dBk[NPIX];   // backward row distance
    __shared__ int s_red[NT / 32];
    __shared__ int s_anyq, s_anyt, s_last;

    if (tid == 0) { s_anyq = 0; s_anyt = 0; }
    __syncthreads();

    // ---- phase 1: threshold into smem masks (coalesced loads) ----
    int aq = 0, at = 0;
    #pragma unroll
    for (int k = 0; k < NPIX / NT; k++) {
        int i = tid + k * NT;
        int q = (srcQ[i] >= TAU);
        int t = (srcT[i] >= TAU);
        mq[i] = (uint8_t)q;
        mt[i] = (uint8_t)t;
        aq |= q; at |= t;
    }
    if (__ballot_sync(0xFFFFFFFFu, aq) && lane == 0) atomicOr(&s_anyq, 1);
    if (__ballot_sync(0xFFFFFFFFu, at) && lane == 0) atomicOr(&s_anyt, 1);
    __syncthreads();

    // ---- phase 2: per-column serial scans (fwd and bwd in parallel warps) ----
    if (tid < W) {
        const int x = tid;
        int d = 1000;
        for (int y = 0; y < H; y++) {
            int idx = y * W + x;
            d = mt[idx] ? 0 : d + 1;
            dF[idx] = (uint8_t)min(d, 255);
        }
    } else if (tid < 2 * W) {
        const int x = tid - W;
        int d = 1000;
        for (int y = H - 1; y >= 0; y--) {
            int idx = y * W + x;
            d = mt[idx] ? 0 : d + 1;
            dBk[idx] = (uint8_t)min(d, 255);
        }
    }
    __syncthreads();

    // ---- phase 3: per-pixel exact early-exit min-plus + local max ----
    int lmax = 0;
    #pragma unroll
    for (int k = 0; k < NPIX / NT; k++) {
        int i = tid + k * NT;
        if (mq[i]) {
            int y = i / W;
            int x = i - y * W;
            int base = y * W;
            int v = min((int)dF[i], (int)dBk[i]);
            int best = v * v;
            for (int dd = 1; dd < W && dd * dd < best; dd++) {
                int dd2 = dd * dd;
                int j = x - dd;
                if (j >= 0) {
                    int u = min((int)dF[base + j], (int)dBk[base + j]);
                    best = min(best, dd2 + u * u);
                }
                j = x + dd;
                if (j < W) {
                    int u = min((int)dF[base + j], (int)dBk[base + j]);
                    best = min(best, dd2 + u * u);
                }
            }
            lmax = max(lmax, best);
        }
    }

    // ---- block max reduction ----
    #pragma unroll
    for (int o = 16; o > 0; o >>= 1)
        lmax = max(lmax, __shfl_xor_sync(0xFFFFFFFFu, lmax, o));
    if (lane == 0) s_red[wid] = lmax;
    __syncthreads();
    if (tid < 32) {
        int v = (tid < NT / 32) ? s_red[tid] : 0;
        #pragma unroll
        for (int o = 16; o > 0; o >>= 1)
            v = max(v, __shfl_xor_sync(0xFFFFFFFFu, v, o));
        if (tid == 0) {
            if (dir == 0) {
                g_maxAB[img] = v;
                g_anyA[img] = s_anyq;
                g_anyB[img] = s_anyt;
            } else {
                g_maxBA[img] = v;
            }
            __threadfence();
            int old = atomicAdd(&g_done, 1);
            s_last = (old == NB - 1);
        }
    }
    __syncthreads();
    if (!s_last) return;
    __threadfence();

    // ---------------- finalize (exactly one block reaches here) ----------------
    __shared__ float hd[B];
    __shared__ int needs[B];    // 0 normal, 1 diam(pred), 2 diam(label)
    if (tid < B) {
        int aa = g_anyA[tid], bb = g_anyB[tid];
        if (aa && bb) {
            hd[tid] = sqrtf((float)max(g_maxAB[tid], g_maxBA[tid]));
            needs[tid] = 0;
        } else if (!aa && !bb) {
            hd[tid] = 0.0f;
            needs[tid] = 0;
        } else {
            needs[tid] = aa ? 1 : 2;
        }
    }
    __syncthreads();

    // empty-set fallback: diameter of the nonempty set (formal correctness;
    // never executes for random-uniform inputs).
    __shared__ int s_diam;
    for (int im = 0; im < B; im++) {
        if (needs[im]) {
            const float* src = (needs[im] == 1) ? (pred + im * NPIX)
                                                : (tgt  + im * NPIX);
            if (tid == 0) s_diam = 0;
            __syncthreads();
            int best = 0;
            for (int p = tid; p < NPIX; p += NT) {
                if (src[p] >= TAU) {
                    int py = p / W, px = p - (p / W) * W;
                    for (int q = 0; q < NPIX; q++) {
                        if (src[q] >= TAU) {
                            int dy = py - q / W;
                            int dxx = px - (q - (q / W) * W);
                            best = max(best, dy * dy + dxx * dxx);
                        }
                    }
                }
            }
            atomicMax(&s_diam, best);
            __syncthreads();
            if (tid == 0) hd[im] = sqrtf((float)s_diam);
            __syncthreads();
        }
    }

    if (tid == 0) {
        float s = 0.0f;
        #pragma unroll
        for (int i = 0; i < B; i++) s += hd[i];
        out[0] = s * (1.0f / B);
        g_done = 0;    // reset for next graph replay
    }
}

// ---------------------------------------------------------------------------
extern "C" void kernel_launch(void* const* d_in, const int* in_sizes, int n_in,
                              void* d_out, int out_size)
{
    const float* pred = (const float*)d_in[0];
    const float* tgt  = (const float*)d_in[1];
    float* out = (float*)d_out;

    hd_all<<<NB, NT>>>(pred, tgt, out);
}

// round 5
// speedup vs baseline: 1.1544x; 1.1544x over previous
#include <cuda_runtime.h>
#include <cuda_bf16.h>
#include <cstdint>
#include <math.h>

#define TAU 0.5f
#define B 16
#define H 96
#define W 96
#define WP (W + 4)          // padded row: 2 sentinel cols each side
#define NPIX (H * W)
#define NB (2 * B)          // 32 blocks: (image, direction)
#define NT 768
#define DCAP 150            // row-dist clamp; 150^2=22500 > max real d2=18050
#define SENT 22500

// static device scratch (no allocation)
__device__ int g_maxAB[B];
__device__ int g_maxBA[B];
__device__ int g_anyA[B];
__device__ int g_anyB[B];
__device__ int g_done = 0;

// dynamic smem layout
#define SM_MQ   0
#define SM_MT   (SM_MQ + NPIX)
#define SM_DF   (SM_MT + NPIX)
#define SM_DB   (SM_DF + NPIX)
#define SM_G2   (SM_DB + NPIX)             // u16[H*WP], 2-byte aligned
#define SM_SIZE (SM_G2 + H * WP * 2)

__global__ void __launch_bounds__(NT, 1)
hd_all(const float* __restrict__ pred,
       const float* __restrict__ tgt,
       float* __restrict__ out)
{
    extern __shared__ char sm[];
    uint8_t*  mq  = (uint8_t*)(sm + SM_MQ);
    uint8_t*  mt  = (uint8_t*)(sm + SM_MT);
    uint8_t*  dF  = (uint8_t*)(sm + SM_DF);
    uint8_t*  dB  = (uint8_t*)(sm + SM_DB);
    uint16_t* g2s = (uint16_t*)(sm + SM_G2);

    __shared__ int s_red[NT / 32];
    __shared__ int s_anyq, s_anyt, s_last;

    const int bx  = blockIdx.x;
    const int img = bx >> 1;
    const int dir = bx & 1;
    const int tid = threadIdx.x;
    const int lane = tid & 31;
    const int wid  = tid >> 5;
    const int x  = tid % W;          // fixed column per thread (NT = 8*W)
    const int y0 = tid / W;          // 0..7; this thread owns rows y0+8k

    const float* srcQ = dir ? (tgt  + img * NPIX) : (pred + img * NPIX);
    const float* srcT = dir ? (pred + img * NPIX) : (tgt  + img * NPIX);

    if (tid == 0) { s_anyq = 0; s_anyt = 0; }

    // ---- phase 1: threshold into smem masks (coalesced) + sentinel borders ----
    int aq = 0, at = 0;
    #pragma unroll
    for (int k = 0; k < NPIX / NT; k++) {
        int i = tid + k * NT;
        int q = (srcQ[i] >= TAU);
        int t = (srcT[i] >= TAU);
        mq[i] = (uint8_t)q;
        mt[i] = (uint8_t)t;
        aq |= q; at |= t;
    }
    if (tid >= NT - 384) {               // 384 border cells: 96 rows x 4
        int b = tid - (NT - 384);
        int yy = b >> 2, c = b & 3;
        int xx = (c < 2) ? c : (W + 2) + (c - 2);
        g2s[yy * WP + xx] = SENT;
    }
    __syncthreads();

    unsigned bq = __ballot_sync(0xFFFFFFFFu, aq);
    unsigned bt = __ballot_sync(0xFFFFFFFFu, at);
    if (lane == 0 && bq) atomicOr(&s_anyq, 1);
    if (lane == 0 && bt) atomicOr(&s_anyt, 1);

    // ---- phase 2a: serial column scans (fwd / bwd in separate warps) ----
    if (tid < W) {
        int d = DCAP;
        #pragma unroll 8
        for (int y = 0; y < H; y++) {
            int idx = y * W + tid;
            d = mt[idx] ? 0 : min(d + 1, DCAP);
            dF[idx] = (uint8_t)d;
        }
    } else if (tid < 2 * W) {
        const int xx = tid - W;
        int d = DCAP;
        #pragma unroll 8
        for (int y = H - 1; y >= 0; y--) {
            int idx = y * W + xx;
            d = mt[idx] ? 0 : min(d + 1, DCAP);
            dB[idx] = (uint8_t)d;
        }
    }
    __syncthreads();

    // ---- phase 2b: combine -> squared row distance in padded array ----
    #pragma unroll
    for (int k = 0; k < NPIX / NT; k++) {
        int i = tid + k * NT;            // = (y0+8k)*W + x
        int y = y0 + 8 * k;
        int d = min((int)dF[i], (int)dB[i]);
        g2s[y * WP + x + 2] = (uint16_t)(d * d);
    }
    __syncthreads();

    // ---- phase 3: branch-free +/-2 window (exact when best<=9) + rare fallback ----
    int lmax = 0;
    #pragma unroll
    for (int k = 0; k < NPIX / NT; k++) {
        int i = tid + k * NT;
        int y = y0 + 8 * k;
        int row = y * WP + x + 2;
        int c  = g2s[row];
        int l1 = g2s[row - 1], r1 = g2s[row + 1];
        int l2 = g2s[row - 2], r2 = g2s[row + 2];
        int best = min(c, min(min(l1, r1) + 1, min(l2, r2) + 4));
        if (best > 9) {                  // rare exact fallback (warp-divergent but ~never)
            for (int dd = 3; dd < W && dd * dd < best; dd++) {
                int dd2 = dd * dd;
                int j = x - dd;
                if (j >= 0) best = min(best, dd2 + (int)g2s[y * WP + j + 2]);
                j = x + dd;
                if (j < W)  best = min(best, dd2 + (int)g2s[y * WP + j + 2]);
            }
        }
        lmax = max(lmax, mq[i] ? best : 0);
    }

    // ---- block max reduction ----
    #pragma unroll
    for (int o = 16; o > 0; o >>= 1)
        lmax = max(lmax, __shfl_xor_sync(0xFFFFFFFFu, lmax, o));
    if (lane == 0) s_red[wid] = lmax;
    __syncthreads();
    if (tid < 32) {
        int v = (tid < NT / 32) ? s_red[tid] : 0;
        #pragma unroll
        for (int o = 16; o > 0; o >>= 1)
            v = max(v, __shfl_xor_sync(0xFFFFFFFFu, v, o));
        if (tid == 0) {
            if (dir == 0) {
                g_maxAB[img] = v;
                g_anyA[img] = s_anyq;
                g_anyB[img] = s_anyt;
            } else {
                g_maxBA[img] = v;
            }
            __threadfence();
            int old = atomicAdd(&g_done, 1);
            s_last = (old == NB - 1);
        }
    }
    __syncthreads();
    if (!s_last) return;
    __threadfence();

    // ---------------- finalize (exactly one block) ----------------
    __shared__ float hd[B];
    __shared__ int needs[B];    // 0 normal, 1 diam(pred), 2 diam(label)
    if (tid < B) {
        int aa = g_anyA[tid], bb = g_anyB[tid];
        if (aa && bb) {
            hd[tid] = sqrtf((float)max(g_maxAB[tid], g_maxBA[tid]));
            needs[tid] = 0;
        } else if (!aa && !bb) {
            hd[tid] = 0.0f;
            needs[tid] = 0;
        } else {
            needs[tid] = aa ? 1 : 2;
        }
    }
    __syncthreads();

    // empty-set fallback: diameter (formal correctness; never runs on this data)
    __shared__ int s_diam;
    for (int im = 0; im < B; im++) {
        if (needs[im]) {
            const float* src = (needs[im] == 1) ? (pred + im * NPIX)
                                                : (tgt  + im * NPIX);
            if (tid == 0) s_diam = 0;
            __syncthreads();
            int best = 0;
            for (int p = tid; p < NPIX; p += NT) {
                if (src[p] >= TAU) {
                    int py = p / W, px = p - (p / W) * W;
                    for (int q = 0; q < NPIX; q++) {
                        if (src[q] >= TAU) {
                            int dy = py - q / W;
                            int dxx = px - (q - (q / W) * W);
                            best = max(best, dy * dy + dxx * dxx);
                        }
                    }
                }
            }
            atomicMax(&s_diam, best);
            __syncthreads();
            if (tid == 0) hd[im] = sqrtf((float)s_diam);
            __syncthreads();
        }
    }

    if (tid == 0) {
        float s = 0.0f;
        #pragma unroll
        for (int i = 0; i < B; i++) s += hd[i];
        out[0] = s * (1.0f / B);
        g_done = 0;    // reset for next graph replay
    }
}

// ---------------------------------------------------------------------------
extern "C" void kernel_launch(void* const* d_in, const int* in_sizes, int n_in,
                              void* d_out, int out_size)
{
    const float* pred = (const float*)d_in[0];
    const float* tgt  = (const float*)d_in[1];
    float* out = (float*)d_out;

    cudaFuncSetAttribute(hd_all, cudaFuncAttributeMaxDynamicSharedMemorySize, SM_SIZE);
    hd_all<<<NB, NT, SM_SIZE>>>(pred, tgt, out);
}

// round 6
// speedup vs baseline: 1.1687x; 1.0124x over previous
#include <cuda_runtime.h>
#include <cuda_bf16.h>
#include <cstdint>
#include <math.h>

#define TAU 0.5f
#define B 16
#define H 96
#define W 96
#define NPIX (H * W)
#define NB (2 * B)          // 32 blocks: (image, direction)
#define NT 768              // 24 warps
#define NW (NT / 32)
#define BIG 100000          // "no pixel in window row" marker (> any real d2)

// static device scratch (no allocation)
__device__ int g_maxAB[B];
__device__ int g_maxBA[B];
__device__ int g_anyA[B];
__device__ int g_anyB[B];
__device__ int g_done = 0;

__global__ void __launch_bounds__(NT, 1)
hd_all(const float* __restrict__ pred,
       const float* __restrict__ tgt,
       float* __restrict__ out)
{
    // target row bitmasks, padded: [y][0]=0, [y][1..3]=bits, [y][4]=0
    __shared__ uint32_t mtp[H * 5];
    __shared__ uint32_t mqw[H * 3];     // query row bitmasks
    __shared__ int s_red[NW];
    __shared__ int s_anyq, s_anyt, s_last;

    const int bx  = blockIdx.x;
    const int img = bx >> 1;
    const int dir = bx & 1;
    const int tid = threadIdx.x;
    const int lane = tid & 31;
    const int wrp  = tid >> 5;

    const float* srcQ = dir ? (tgt  + img * NPIX) : (pred + img * NPIX);
    const float* srcT = dir ? (pred + img * NPIX) : (tgt  + img * NPIX);

    if (tid == 0) { s_anyq = 0; s_anyt = 0; }
    if (tid < H) { mtp[tid * 5 + 0] = 0u; mtp[tid * 5 + 4] = 0u; }

    // ---- phase 1: load + threshold + ballot into row bitmasks ----
    // i = tid + k*NT is 32-aligned per warp, so ballot lane == x%32 exactly.
    unsigned aq = 0, at = 0;
    #pragma unroll
    for (int k = 0; k < NPIX / NT; k++) {
        int i = tid + k * NT;
        unsigned bq = __ballot_sync(0xFFFFFFFFu, srcQ[i] >= TAU);
        unsigned bt = __ballot_sync(0xFFFFFFFFu, srcT[i] >= TAU);
        aq |= bq; at |= bt;
        if (lane == 0) {
            int wi = (i >> 5);            // linear word index = y*3 + xw
            int y  = wi / 3, xw = wi - y * 3;
            mqw[wi] = bq;
            mtp[y * 5 + 1 + xw] = bt;
        }
    }
    if (lane == 0 && aq) atomicOr(&s_anyq, 1);
    if (lane == 0 && at) atomicOr(&s_anyt, 1);
    __syncthreads();

    // ---- phase 2: per-pixel 5x5 window (exact when best<=8) ----
    // thread -> fixed column x, 12 consecutive rows [yb, yb+12)
    const int x  = tid % W;
    const int yb = (tid / W) * (H / 8);   // tid/W in 0..7, 12 rows each
    const int xw = x >> 5, xb = x & 31;
    const int pos = x + 30;               // window start (x-2) biased by padding word
    const int q  = pos >> 5;
    const int sh = pos & 31;

    // tval(y): min dx^2 over target bits in columns [x-2, x+2] of row y
    auto tval = [&](int y) -> int {
        if (y < 0 || y > H - 1) return BIG;
        uint32_t lo = mtp[y * 5 + q], hi = mtp[y * 5 + q + 1];
        uint32_t b = __funnelshift_r(lo, hi, sh) & 31u;
        return (b & 4u) ? 0 : ((b & 10u) ? 1 : ((b & 17u) ? 4 : BIG));
    };

    int tv[5];
    tv[0] = tval(yb - 2); tv[1] = tval(yb - 1); tv[2] = tval(yb);
    tv[3] = tval(yb + 1); tv[4] = tval(yb + 2);

    int lmax = 0;
    #pragma unroll
    for (int k = 0; k < H / 8; k++) {
        int y = yb + k;
        int c  = tv[(k + 2) % 5];
        int p1 = min(tv[(k + 1) % 5], tv[(k + 3) % 5]);
        int p2 = min(tv[(k + 0) % 5], tv[(k + 4) % 5]);
        int best = min(c, min(p1 + 1, p2 + 4));
        if (best > 8) {
            // exact rare fallback: full search over target bitmask
            for (int yy = 0; yy < H; yy++) {
                int dy2 = (yy - y) * (yy - y);
                if (dy2 >= best) continue;
                #pragma unroll
                for (int w = 0; w < 3; w++) {
                    uint32_t m = mtp[yy * 5 + 1 + w];
                    while (m) {
                        int bpos = __ffs(m) - 1; m &= m - 1;
                        int dx = w * 32 + bpos - x;
                        best = min(best, dy2 + dx * dx);
                    }
                }
            }
        }
        int qbit = (mqw[y * 3 + xw] >> xb) & 1;
        lmax = max(lmax, qbit ? best : 0);
        tv[k % 5] = tval(y + 3);
    }

    // ---- block max reduction ----
    #pragma unroll
    for (int o = 16; o > 0; o >>= 1)
        lmax = max(lmax, __shfl_xor_sync(0xFFFFFFFFu, lmax, o));
    if (lane == 0) s_red[wrp] = lmax;
    __syncthreads();
    if (tid < 32) {
        int v = (tid < NW) ? s_red[tid] : 0;
        #pragma unroll
        for (int o = 16; o > 0; o >>= 1)
            v = max(v, __shfl_xor_sync(0xFFFFFFFFu, v, o));
        if (tid == 0) {
            if (dir == 0) {
                g_maxAB[img] = v;
                g_anyA[img] = s_anyq;
                g_anyB[img] = s_anyt;
            } else {
                g_maxBA[img] = v;
            }
            __threadfence();
            int old = atomicAdd(&g_done, 1);
            s_last = (old == NB - 1);
        }
    }
    __syncthreads();
    if (!s_last) return;
    __threadfence();

    // ---------------- finalize (exactly one block) ----------------
    __shared__ float hd[B];
    __shared__ int needs[B];    // 0 normal, 1 diam(pred), 2 diam(label)
    if (tid < B) {
        int aa = g_anyA[tid], bb = g_anyB[tid];
        if (aa && bb) {
            hd[tid] = sqrtf((float)max(g_maxAB[tid], g_maxBA[tid]));
            needs[tid] = 0;
        } else if (!aa && !bb) {
            hd[tid] = 0.0f;
            needs[tid] = 0;
        } else {
            needs[tid] = aa ? 1 : 2;
        }
    }
    __syncthreads();

    // empty-set fallback: diameter (formal correctness; never runs on this data)
    __shared__ int s_diam;
    for (int im = 0; im < B; im++) {
        if (needs[im]) {
            const float* src = (needs[im] == 1) ? (pred + im * NPIX)
                                                : (tgt  + im * NPIX);
            if (tid == 0) s_diam = 0;
            __syncthreads();
            int best = 0;
            for (int p = tid; p < NPIX; p += NT) {
                if (src[p] >= TAU) {
                    int py = p / W, px = p - (p / W) * W;
                    for (int qq = 0; qq < NPIX; qq++) {
                        if (src[qq] >= TAU) {
                            int dy = py - qq / W;
                            int dxx = px - (qq - (qq / W) * W);
                            best = max(best, dy * dy + dxx * dxx);
                        }
                    }
                }
            }
            atomicMax(&s_diam, best);
            __syncthreads();
            if (tid == 0) hd[im] = sqrtf((float)s_diam);
            __syncthreads();
        }
    }

    if (tid == 0) {
        float s = 0.0f;
        #pragma unroll
        for (int i = 0; i < B; i++) s += hd[i];
        out[0] = s * (1.0f / B);
        g_done = 0;    // reset for next graph replay
    }
}

// ---------------------------------------------------------------------------
extern "C" void kernel_launch(void* const* d_in, const int* in_sizes, int n_in,
                              void* d_out, int out_size)
{
    const float* pred = (const float*)d_in[0];
    const float* tgt  = (const float*)d_in[1];
    float* out = (float*)d_out;

    hd_all<<<NB, NT>>>(pred, tgt, out);
}